// round 1
// baseline (speedup 1.0000x reference)
#include <cuda_runtime.h>
#include <math.h>

// Problem shape (fixed)
#define Bb    4
#define Ss    4096
#define Dd    1024
#define Mtot  (Bb * Ss)        // 16384 rows
#define CHUNKS 64
#define TT     64              // Ss / CHUNKS
#define NCH   (Bb * Dd)        // 4096 channels

// GEMM tiling
#define BM 128
#define BN 64
#define BK 16

// Scratch (allocation-free rule: __device__ globals)
__device__ float g_xs[Mtot * Dd];            // sigmoid(g)*tanh(v)
__device__ float g_a [Mtot * Dd];            // decay a; overwritten with in-chunk cumprod P
__device__ float g_carry[CHUNKS * NCH];      // per-chunk incoming carry

__device__ __forceinline__ float sigmoidf_(float x) {
    return 1.0f / (1.0f + __expf(-x));
}

// ---------------------------------------------------------------------------
// Kernel 1: fused triple GEMM (g, v, d) + gating epilogue.
//   y = x @ W^T + b  for W in {Wg, Wv, Wd};  A and B are both K-major (NT GEMM).
//   Epilogue: g_xs = sigmoid(g)*tanh(v); g_a = 0.001 + 0.998*sigmoid(d)
// ---------------------------------------------------------------------------
__global__ __launch_bounds__(256)
void gemm_gate_kernel(const float* __restrict__ x,
                      const float* __restrict__ Wg, const float* __restrict__ bg,
                      const float* __restrict__ Wv, const float* __restrict__ bv,
                      const float* __restrict__ Wd, const float* __restrict__ bd)
{
    __shared__ float As[BK][BM];        // 8 KB
    __shared__ float Bs[3][BK][BN];     // 12 KB

    const int m0  = blockIdx.y * BM;
    const int n0  = blockIdx.x * BN;
    const int tid = threadIdx.x;
    const int tm  = tid >> 4;   // 0..15 -> 8 rows each
    const int tn  = tid & 15;   // 0..15 -> 4 cols each

    float accg[8][4] = {}, accv[8][4] = {}, accd[8][4] = {};

    for (int k0 = 0; k0 < Dd; k0 += BK) {
        // --- load A tile: 128x16 floats = 512 float4, 2 per thread ---
        #pragma unroll
        for (int ld = 0; ld < 2; ld++) {
            int idx = tid + ld * 256;
            int r   = idx >> 2;        // 0..127
            int c4  = idx & 3;         // 0..3
            float4 v = *(const float4*)&x[(m0 + r) * Dd + k0 + c4 * 4];
            As[c4 * 4 + 0][r] = v.x;
            As[c4 * 4 + 1][r] = v.y;
            As[c4 * 4 + 2][r] = v.z;
            As[c4 * 4 + 3][r] = v.w;
        }
        // --- load B tiles: 64x16 per weight = 256 float4, 1 per thread ---
        {
            int r  = tid >> 2;         // 0..63
            int c4 = tid & 3;
            float4 v0 = *(const float4*)&Wg[(n0 + r) * Dd + k0 + c4 * 4];
            Bs[0][c4 * 4 + 0][r] = v0.x; Bs[0][c4 * 4 + 1][r] = v0.y;
            Bs[0][c4 * 4 + 2][r] = v0.z; Bs[0][c4 * 4 + 3][r] = v0.w;
            float4 v1 = *(const float4*)&Wv[(n0 + r) * Dd + k0 + c4 * 4];
            Bs[1][c4 * 4 + 0][r] = v1.x; Bs[1][c4 * 4 + 1][r] = v1.y;
            Bs[1][c4 * 4 + 2][r] = v1.z; Bs[1][c4 * 4 + 3][r] = v1.w;
            float4 v2 = *(const float4*)&Wd[(n0 + r) * Dd + k0 + c4 * 4];
            Bs[2][c4 * 4 + 0][r] = v2.x; Bs[2][c4 * 4 + 1][r] = v2.y;
            Bs[2][c4 * 4 + 2][r] = v2.z; Bs[2][c4 * 4 + 3][r] = v2.w;
        }
        __syncthreads();

        #pragma unroll
        for (int k = 0; k < BK; k++) {
            float4 a0 = *(const float4*)&As[k][tm * 8];
            float4 a1 = *(const float4*)&As[k][tm * 8 + 4];
            float4 b0 = *(const float4*)&Bs[0][k][tn * 4];
            float4 b1 = *(const float4*)&Bs[1][k][tn * 4];
            float4 b2 = *(const float4*)&Bs[2][k][tn * 4];
            float af[8] = {a0.x, a0.y, a0.z, a0.w, a1.x, a1.y, a1.z, a1.w};
            float bgf[4] = {b0.x, b0.y, b0.z, b0.w};
            float bvf[4] = {b1.x, b1.y, b1.z, b1.w};
            float bdf[4] = {b2.x, b2.y, b2.z, b2.w};
            #pragma unroll
            for (int i = 0; i < 8; i++) {
                #pragma unroll
                for (int j = 0; j < 4; j++) {
                    accg[i][j] = fmaf(af[i], bgf[j], accg[i][j]);
                    accv[i][j] = fmaf(af[i], bvf[j], accv[i][j]);
                    accd[i][j] = fmaf(af[i], bdf[j], accd[i][j]);
                }
            }
        }
        __syncthreads();
    }

    // --- epilogue: gating math, write xs and a ---
    const int e = n0 + tn * 4;
    const float4 bgv = *(const float4*)&bg[e];
    const float4 bvv = *(const float4*)&bv[e];
    const float4 bdv = *(const float4*)&bd[e];
    const float bgf[4] = {bgv.x, bgv.y, bgv.z, bgv.w};
    const float bvf[4] = {bvv.x, bvv.y, bvv.z, bvv.w};
    const float bdf[4] = {bdv.x, bdv.y, bdv.z, bdv.w};

    #pragma unroll
    for (int i = 0; i < 8; i++) {
        int row = m0 + tm * 8 + i;
        float xs4[4], a4[4];
        #pragma unroll
        for (int j = 0; j < 4; j++) {
            float gg = accg[i][j] + bgf[j];
            float vv = accv[i][j] + bvf[j];
            float dd = accd[i][j] + bdf[j];
            xs4[j] = sigmoidf_(gg) * tanhf(vv);
            a4[j]  = 0.001f + 0.998f * sigmoidf_(dd);
        }
        *(float4*)&g_xs[row * Dd + e] = make_float4(xs4[0], xs4[1], xs4[2], xs4[3]);
        *(float4*)&g_a [row * Dd + e] = make_float4(a4[0],  a4[1],  a4[2],  a4[3]);
    }
}

// ---------------------------------------------------------------------------
// Kernel 2 (scan pass 1): per (channel, chunk) local scan.
//   L_t = a_t * L_{t-1} + x_t  (L_{-1} = 0 within chunk), P_t = prod a up to t.
//   Writes L into out, overwrites g_a with P in-place.
// ---------------------------------------------------------------------------
__global__ __launch_bounds__(256)
void scan_chunk_kernel(float* __restrict__ out)
{
    int gid = blockIdx.x * blockDim.x + threadIdx.x;   // (c*Bb + b)*Dd + d
    int d    = gid & (Dd - 1);
    int rest = gid >> 10;
    int b    = rest & (Bb - 1);
    int c    = rest >> 2;

    int base = (b * Ss + c * TT) * Dd + d;
    float h = 0.0f, p = 1.0f;
    #pragma unroll 8
    for (int t = 0; t < TT; t++) {
        int idx = base + t * Dd;
        float a  = g_a[idx];
        float xv = g_xs[idx];
        h = fmaf(a, h, xv);
        p = p * a;
        out[idx] = h;
        g_a[idx] = p;
    }
}

// ---------------------------------------------------------------------------
// Kernel 3 (scan pass 2): per-channel scan over chunk summaries.
//   carry[c] = h entering chunk c;  carry[c+1] = L_last(c) + P_last(c)*carry[c]
// ---------------------------------------------------------------------------
__global__ __launch_bounds__(256)
void scan_carry_kernel(const float* __restrict__ out)
{
    int ch = blockIdx.x * blockDim.x + threadIdx.x;  // 0..NCH-1
    int d = ch & (Dd - 1);
    int b = ch >> 10;

    float cur = 0.0f;
    g_carry[ch] = 0.0f;  // chunk 0 carry
    #pragma unroll 8
    for (int c = 0; c < CHUNKS; c++) {
        int idx = (b * Ss + c * TT + TT - 1) * Dd + d;
        float P = g_a[idx];
        float L = out[idx];
        cur = fmaf(P, cur, L);
        if (c + 1 < CHUNKS) g_carry[(c + 1) * NCH + ch] = cur;
    }
}

// ---------------------------------------------------------------------------
// Kernel 4 (scan pass 3): fixup  out_t = L_t + carry[chunk] * P_t  (chunks >= 1)
// ---------------------------------------------------------------------------
__global__ __launch_bounds__(256)
void scan_fix_kernel(float* __restrict__ out)
{
    int e4  = blockIdx.x * blockDim.x + threadIdx.x;  // float4 index
    int idx = e4 * 4;
    int m = idx >> 10;           // row index (b*Ss + s)
    int s = m & (Ss - 1);
    int c = s >> 6;              // s / TT
    if (c == 0) return;
    int b = m >> 12;             // m / Ss
    int d = idx & (Dd - 1);

    float4 P  = *(const float4*)&g_a[idx];
    float4 L  = *(float4*)&out[idx];
    float4 cr = *(const float4*)&g_carry[c * NCH + b * Dd + d];
    L.x = fmaf(cr.x, P.x, L.x);
    L.y = fmaf(cr.y, P.y, L.y);
    L.z = fmaf(cr.z, P.z, L.z);
    L.w = fmaf(cr.w, P.w, L.w);
    *(float4*)&out[idx] = L;
}

// ---------------------------------------------------------------------------
extern "C" void kernel_launch(void* const* d_in, const int* in_sizes, int n_in,
                              void* d_out, int out_size)
{
    const float* x  = (const float*)d_in[0];
    const float* Wg = (const float*)d_in[1];
    const float* bg = (const float*)d_in[2];
    const float* Wv = (const float*)d_in[3];
    const float* bv = (const float*)d_in[4];
    const float* Wd = (const float*)d_in[5];
    const float* bd = (const float*)d_in[6];
    float* out = (float*)d_out;

    dim3 gemm_grid(Dd / BN, Mtot / BM);   // (16, 128)
    gemm_gate_kernel<<<gemm_grid, 256>>>(x, Wg, bg, Wv, bv, Wd, bd);

    scan_chunk_kernel<<<(NCH * CHUNKS) / 256, 256>>>(out);
    scan_carry_kernel<<<NCH / 256, 256>>>(out);
    scan_fix_kernel  <<<(Mtot * Dd / 4) / 256, 256>>>(out);
}

// round 4
// speedup vs baseline: 3.4079x; 3.4079x over previous
#include <cuda_runtime.h>
#include <cuda_bf16.h>
#include <math.h>
#include <cstdint>

// Problem shape (fixed)
#define Bb    4
#define Ss    4096
#define Dd    1024
#define Mtot  (Bb * Ss)        // 16384 rows
#define CHUNKS 64
#define TT     64
#define NCH   (Bb * Dd)

// GEMM tiling
#define TBM 128
#define TBN 128
#define KC  64                 // K chunk: 64 bf16 = 128B rows (SW128 swizzle)
#define NKC (Dd / KC)          // 16
#define STAGES 3
#define STAGE_BYTES 65536      // 4 operand tiles x 16KB
#define OFF_AHI 0
#define OFF_ALO 16384
#define OFF_BHI 32768
#define OFF_BLO 49152
#define SMEM_TOTAL (STAGES * STAGE_BYTES)   // 196608

// Scratch (__device__ globals; no allocation allowed)
__device__ float g_xs[Mtot * Dd];
__device__ float g_a [Mtot * Dd];
__device__ float g_carry[CHUNKS * NCH];
__device__ float g_lin[3ll * Mtot * Dd];          // raw GEMM outputs g,v,d
__device__ __nv_bfloat16 g_xhi[Mtot * Dd];
__device__ __nv_bfloat16 g_xlo[Mtot * Dd];
__device__ __nv_bfloat16 g_whi[3 * Dd * Dd];
__device__ __nv_bfloat16 g_wlo[3 * Dd * Dd];

// ---------------- helpers ----------------
__device__ __forceinline__ uint32_t smem_u32(const void* p) {
    uint32_t a;
    asm("{ .reg .u64 t; cvta.to.shared.u64 t, %1; cvt.u32.u64 %0, t; }" : "=r"(a) : "l"(p));
    return a;
}
__device__ __forceinline__ void cp_async16(uint32_t s, const void* g) {
    asm volatile("{ .reg .u64 ga; cvta.to.global.u64 ga, %1; "
                 "cp.async.cg.shared.global [%0], [ga], 16; }"
                 :: "r"(s), "l"(g) : "memory");
}
#define CP_COMMIT() asm volatile("cp.async.commit_group;" ::: "memory")

#define LDSM4(r, addr) \
    asm volatile("ldmatrix.sync.aligned.m8n8.x4.shared.b16 {%0,%1,%2,%3}, [%4];" \
        : "=r"((r)[0]), "=r"((r)[1]), "=r"((r)[2]), "=r"((r)[3]) : "r"(addr))

__device__ __forceinline__ void mma_bf16(float* c, const uint32_t* a,
                                         uint32_t b0, uint32_t b1) {
    asm volatile("mma.sync.aligned.m16n8k16.row.col.f32.bf16.bf16.f32 "
        "{%0,%1,%2,%3}, {%4,%5,%6,%7}, {%8,%9}, {%0,%1,%2,%3};"
        : "+f"(c[0]), "+f"(c[1]), "+f"(c[2]), "+f"(c[3])
        : "r"(a[0]), "r"(a[1]), "r"(a[2]), "r"(a[3]), "r"(b0), "r"(b1));
}

__device__ __forceinline__ float sigmoidf_(float x) { return 1.0f / (1.0f + __expf(-x)); }
__device__ __forceinline__ unsigned short bf16_bits(__nv_bfloat16 h) {
    return *reinterpret_cast<unsigned short*>(&h);
}
__device__ __forceinline__ void split_bf16(float v, unsigned short& hi, unsigned short& lo) {
    __nv_bfloat16 h = __float2bfloat16(v);
    float r = v - __bfloat162float(h);
    __nv_bfloat16 l = __float2bfloat16(r);
    hi = bf16_bits(h); lo = bf16_bits(l);
}

// ---------------------------------------------------------------------------
// fp32 -> bf16 hi/lo split conversions
// ---------------------------------------------------------------------------
__global__ __launch_bounds__(256)
void convert_x_kernel(const float* __restrict__ x) {
    int i = blockIdx.x * blockDim.x + threadIdx.x;
    float4 v = ((const float4*)x)[i];
    ushort4 hi, lo;
    split_bf16(v.x, hi.x, lo.x); split_bf16(v.y, hi.y, lo.y);
    split_bf16(v.z, hi.z, lo.z); split_bf16(v.w, hi.w, lo.w);
    ((ushort4*)g_xhi)[i] = hi;
    ((ushort4*)g_xlo)[i] = lo;
}

__global__ __launch_bounds__(256)
void convert_w_kernel(const float* __restrict__ Wg, const float* __restrict__ Wv,
                      const float* __restrict__ Wd) {
    int i = blockIdx.x * blockDim.x + threadIdx.x;
    const int per = Dd * Dd / 4;
    int mat = i / per, rem = i - mat * per;
    const float* src = (mat == 0) ? Wg : (mat == 1) ? Wv : Wd;
    float4 v = ((const float4*)src)[rem];
    ushort4 hi, lo;
    split_bf16(v.x, hi.x, lo.x); split_bf16(v.y, hi.y, lo.y);
    split_bf16(v.z, hi.z, lo.z); split_bf16(v.w, hi.w, lo.w);
    ((ushort4*)g_whi)[i] = hi;
    ((ushort4*)g_wlo)[i] = lo;
}

// ---------------------------------------------------------------------------
// Stage loader: 4 operand tiles (A_hi, A_lo, B_hi, B_lo), 128 rows x 128B,
// SW128-swizzled, via cp.async (16 x 16B per thread).
// ---------------------------------------------------------------------------
__device__ __forceinline__ void issue_stage(uint32_t sbase, int s,
    const __nv_bfloat16* a_hi, const __nv_bfloat16* a_lo,
    const __nv_bfloat16* b_hi, const __nv_bfloat16* b_lo,
    int kc, int tid)
{
    const __nv_bfloat16* srcs[4] = {a_hi, a_lo, b_hi, b_lo};
    uint32_t base = sbase + s * STAGE_BYTES;
    #pragma unroll
    for (int o = 0; o < 4; o++) {
        const __nv_bfloat16* src = srcs[o] + kc * KC;
        uint32_t dbase = base + o * 16384;
        #pragma unroll
        for (int it = 0; it < 4; it++) {
            int u = tid + it * 256;
            int r = u >> 3, seg = u & 7;
            uint32_t dst = dbase + r * 128 + ((uint32_t)(seg ^ (r & 7)) << 4);
            cp_async16(dst, src + (size_t)r * Dd + seg * 8);
        }
    }
}

// ---------------------------------------------------------------------------
// bf16-split mma.sync GEMM: C[m,n] = sum_k A[m,k]*W[n,k]  (one of g/v/d per z)
// CTA 128x128, 8 warps (2x4), warp tile 64x32, 3-stage cp.async pipeline.
// ---------------------------------------------------------------------------
__global__ __launch_bounds__(256, 1)
void gemm_mma_kernel()
{
    extern __shared__ char smem[];
    const uint32_t sbase = smem_u32(smem);
    const int tid = threadIdx.x, lane = tid & 31, wid = tid >> 5;
    const int wm = wid >> 2, wn = wid & 3;
    const int m0 = blockIdx.y * TBM, n0 = blockIdx.x * TBN, mat = blockIdx.z;

    const __nv_bfloat16* a_hi = g_xhi + (size_t)m0 * Dd;
    const __nv_bfloat16* a_lo = g_xlo + (size_t)m0 * Dd;
    const __nv_bfloat16* b_hi = g_whi + ((size_t)mat * Dd + n0) * Dd;
    const __nv_bfloat16* b_lo = g_wlo + ((size_t)mat * Dd + n0) * Dd;

    issue_stage(sbase, 0, a_hi, a_lo, b_hi, b_lo, 0, tid); CP_COMMIT();
    issue_stage(sbase, 1, a_hi, a_lo, b_hi, b_lo, 1, tid); CP_COMMIT();

    float acc[4][4][4] = {};

    // per-lane ldmatrix addressing
    const int r8 = lane & 7, q = lane >> 3;
    const int a_row_loc = (q & 1) * 8 + r8;   // within a 16-row m tile
    const int a_seg_add = q >> 1;             // k-seg half
    const int b_row_loc = (q >> 1) * 8 + r8;  // within a 16-row n block
    const int b_seg_add = q & 1;
    const uint32_t a_off0 = (uint32_t)(wm * 64 + a_row_loc) * 128;
    const uint32_t b_off0 = (uint32_t)(wn * 32 + b_row_loc) * 128;

    for (int kc = 0; kc < NKC; kc++) {
        if (kc + 2 < NKC) {
            issue_stage(sbase, (kc + 2) % STAGES, a_hi, a_lo, b_hi, b_lo, kc + 2, tid);
            CP_COMMIT();
            asm volatile("cp.async.wait_group 2;" ::: "memory");
        } else if (kc + 1 < NKC) {
            asm volatile("cp.async.wait_group 1;" ::: "memory");
        } else {
            asm volatile("cp.async.wait_group 0;" ::: "memory");
        }
        __syncthreads();

        const uint32_t st = sbase + (kc % STAGES) * STAGE_BYTES;
        #pragma unroll
        for (int ks = 0; ks < 4; ks++) {          // 4 x k16 steps within KC=64
            uint32_t ahi[4][4], alo[4][4];
            #pragma unroll
            for (int mi = 0; mi < 4; mi++) {
                uint32_t off = a_off0 + mi * (16 * 128)
                             + ((uint32_t)((ks * 2 + a_seg_add) ^ r8) << 4);
                LDSM4(ahi[mi], st + OFF_AHI + off);
                LDSM4(alo[mi], st + OFF_ALO + off);
            }
            uint32_t bhi[2][4], blo[2][4];
            #pragma unroll
            for (int j = 0; j < 2; j++) {
                uint32_t off = b_off0 + j * (16 * 128)
                             + ((uint32_t)((ks * 2 + b_seg_add) ^ r8) << 4);
                LDSM4(bhi[j], st + OFF_BHI + off);
                LDSM4(blo[j], st + OFF_BLO + off);
            }
            #pragma unroll
            for (int mi = 0; mi < 4; mi++) {
                #pragma unroll
                for (int ni = 0; ni < 4; ni++) {
                    const int j = ni >> 1, sub = ni & 1;
                    mma_bf16(acc[mi][ni], ahi[mi], bhi[j][sub*2], bhi[j][sub*2+1]);
                    mma_bf16(acc[mi][ni], ahi[mi], blo[j][sub*2], blo[j][sub*2+1]);
                    mma_bf16(acc[mi][ni], alo[mi], bhi[j][sub*2], bhi[j][sub*2+1]);
                }
            }
        }
        __syncthreads();
    }

    // epilogue: write raw fp32 GEMM result
    float* C = g_lin + (size_t)mat * Mtot * Dd;
    const int row_base = m0 + wm * 64 + (lane >> 2);
    const int col_base = n0 + wn * 32 + (lane & 3) * 2;
    #pragma unroll
    for (int mi = 0; mi < 4; mi++) {
        const int row = row_base + mi * 16;
        #pragma unroll
        for (int ni = 0; ni < 4; ni++) {
            const int col = col_base + ni * 8;
            *(float2*)&C[(size_t)row * Dd + col] =
                make_float2(acc[mi][ni][0], acc[mi][ni][1]);
            *(float2*)&C[(size_t)(row + 8) * Dd + col] =
                make_float2(acc[mi][ni][2], acc[mi][ni][3]);
        }
    }
}

// ---------------------------------------------------------------------------
// Gating: xs = sigmoid(g+bg)*tanh(v+bv); a = 0.001 + 0.998*sigmoid(d+bd)
// ---------------------------------------------------------------------------
__global__ __launch_bounds__(256)
void gate_kernel(const float* __restrict__ bg, const float* __restrict__ bv,
                 const float* __restrict__ bd)
{
    int i = blockIdx.x * blockDim.x + threadIdx.x;   // float4 index
    int col = (i << 2) & (Dd - 1);
    float4 g = ((const float4*)g_lin)[i];
    float4 v = ((const float4*)(g_lin + (size_t)Mtot * Dd))[i];
    float4 d = ((const float4*)(g_lin + 2 * (size_t)Mtot * Dd))[i];
    float4 BG = *(const float4*)&bg[col];
    float4 BV = *(const float4*)&bv[col];
    float4 BD = *(const float4*)&bd[col];

    float4 xs, a;
    xs.x = sigmoidf_(g.x + BG.x) * tanhf(v.x + BV.x);
    xs.y = sigmoidf_(g.y + BG.y) * tanhf(v.y + BV.y);
    xs.z = sigmoidf_(g.z + BG.z) * tanhf(v.z + BV.z);
    xs.w = sigmoidf_(g.w + BG.w) * tanhf(v.w + BV.w);
    a.x = 0.001f + 0.998f * sigmoidf_(d.x + BD.x);
    a.y = 0.001f + 0.998f * sigmoidf_(d.y + BD.y);
    a.z = 0.001f + 0.998f * sigmoidf_(d.z + BD.z);
    a.w = 0.001f + 0.998f * sigmoidf_(d.w + BD.w);

    ((float4*)g_xs)[i] = xs;
    ((float4*)g_a)[i]  = a;
}

// ---------------------------------------------------------------------------
// Scan pass 1: per (channel, chunk) local scan; P overwrites g_a in place.
// ---------------------------------------------------------------------------
__global__ __launch_bounds__(256)
void scan_chunk_kernel(float* __restrict__ out)
{
    int gid = blockIdx.x * blockDim.x + threadIdx.x;
    int d    = gid & (Dd - 1);
    int rest = gid >> 10;
    int b    = rest & (Bb - 1);
    int c    = rest >> 2;

    int base = (b * Ss + c * TT) * Dd + d;
    float h = 0.0f, p = 1.0f;
    #pragma unroll 8
    for (int t = 0; t < TT; t++) {
        int idx = base + t * Dd;
        float a  = g_a[idx];
        float xv = g_xs[idx];
        h = fmaf(a, h, xv);
        p = p * a;
        out[idx] = h;
        g_a[idx] = p;
    }
}

// ---------------------------------------------------------------------------
// Scan pass 2: per-channel scan over chunk summaries -> carries.
// ---------------------------------------------------------------------------
__global__ __launch_bounds__(256)
void scan_carry_kernel(const float* __restrict__ out)
{
    int ch = blockIdx.x * blockDim.x + threadIdx.x;
    int d = ch & (Dd - 1);
    int b = ch >> 10;

    float cur = 0.0f;
    g_carry[ch] = 0.0f;
    #pragma unroll 8
    for (int c = 0; c < CHUNKS; c++) {
        int idx = (b * Ss + c * TT + TT - 1) * Dd + d;
        float P = g_a[idx];
        float L = out[idx];
        cur = fmaf(P, cur, L);
        if (c + 1 < CHUNKS) g_carry[(c + 1) * NCH + ch] = cur;
    }
}

// ---------------------------------------------------------------------------
// Scan pass 3: fixup  out_t += carry[chunk] * P_t  (chunks >= 1)
// ---------------------------------------------------------------------------
__global__ __launch_bounds__(256)
void scan_fix_kernel(float* __restrict__ out)
{
    int e4  = blockIdx.x * blockDim.x + threadIdx.x;
    int idx = e4 * 4;
    int m = idx >> 10;
    int s = m & (Ss - 1);
    int c = s >> 6;
    if (c == 0) return;
    int b = m >> 12;
    int d = idx & (Dd - 1);

    float4 P  = *(const float4*)&g_a[idx];
    float4 L  = *(float4*)&out[idx];
    float4 cr = *(const float4*)&g_carry[c * NCH + b * Dd + d];
    L.x = fmaf(cr.x, P.x, L.x);
    L.y = fmaf(cr.y, P.y, L.y);
    L.z = fmaf(cr.z, P.z, L.z);
    L.w = fmaf(cr.w, P.w, L.w);
    *(float4*)&out[idx] = L;
}

// ---------------------------------------------------------------------------
extern "C" void kernel_launch(void* const* d_in, const int* in_sizes, int n_in,
                              void* d_out, int out_size)
{
    const float* x  = (const float*)d_in[0];
    const float* Wg = (const float*)d_in[1];
    const float* bg = (const float*)d_in[2];
    const float* Wv = (const float*)d_in[3];
    const float* bv = (const float*)d_in[4];
    const float* Wd = (const float*)d_in[5];
    const float* bd = (const float*)d_in[6];
    float* out = (float*)d_out;

    cudaFuncSetAttribute(gemm_mma_kernel,
                         cudaFuncAttributeMaxDynamicSharedMemorySize, SMEM_TOTAL);

    convert_x_kernel<<<Mtot * Dd / 4 / 256, 256>>>(x);
    convert_w_kernel<<<3 * Dd * Dd / 4 / 256, 256>>>(Wg, Wv, Wd);

    dim3 grid(Dd / TBN, Mtot / TBM, 3);   // (8, 128, 3)
    gemm_mma_kernel<<<grid, 256, SMEM_TOTAL>>>();

    gate_kernel<<<Mtot * Dd / 4 / 256, 256>>>(bg, bv, bd);

    scan_chunk_kernel<<<(NCH * CHUNKS) / 256, 256>>>(out);
    scan_carry_kernel<<<NCH / 256, 256>>>(out);
    scan_fix_kernel  <<<(Mtot * Dd / 4) / 256, 256>>>(out);
}

// round 6
// speedup vs baseline: 3.6155x; 1.0609x over previous
#include <cuda_runtime.h>
#include <cuda_bf16.h>
#include <math.h>
#include <cstdint>

// Problem shape (fixed)
#define Bb    4
#define Ss    4096
#define Dd    1024
#define Mtot  (Bb * Ss)        // 16384 rows
#define MD    ((size_t)Mtot * Dd)
#define CHUNKS 64
#define TT     64
#define NCH   (Bb * Dd)

// GEMM tiling
#define TBM 128
#define TBN 128
#define KC  32                 // K chunk: 32 bf16 = 64B rows
#define NKC (Dd / KC)          // 32
#define STAGES 3
#define TILE_BYTES 8192        // 128 rows x 64B
#define STAGE_BYTES (4 * TILE_BYTES)        // 32KB
#define OFF_AHI 0
#define OFF_ALO 8192
#define OFF_BHI 16384
#define OFF_BLO 24576
#define SMEM_TOTAL (STAGES * STAGE_BYTES)   // 98304 -> 2 CTAs/SM

// Scratch (__device__ globals; no allocation allowed)
__device__ float g_a [Mtot * Dd];            // decay a -> in-chunk cumprod P
__device__ float g_carry[CHUNKS * NCH];
__device__ float g_lin[3ll * Mtot * Dd];     // raw GEMM outputs g,v,d
__device__ __nv_bfloat16 g_xhi[Mtot * Dd];
__device__ __nv_bfloat16 g_xlo[Mtot * Dd];
__device__ __nv_bfloat16 g_whi[3 * Dd * Dd];
__device__ __nv_bfloat16 g_wlo[3 * Dd * Dd];

// ---------------- helpers ----------------
__device__ __forceinline__ uint32_t smem_u32(const void* p) {
    uint32_t a;
    asm("{ .reg .u64 t; cvta.to.shared.u64 t, %1; cvt.u32.u64 %0, t; }" : "=r"(a) : "l"(p));
    return a;
}
__device__ __forceinline__ void cp_async16(uint32_t s, const void* g) {
    asm volatile("{ .reg .u64 ga; cvta.to.global.u64 ga, %1; "
                 "cp.async.cg.shared.global [%0], [ga], 16; }"
                 :: "r"(s), "l"(g) : "memory");
}
#define CP_COMMIT() asm volatile("cp.async.commit_group;" ::: "memory")

#define LDSM4(r, addr) \
    asm volatile("ldmatrix.sync.aligned.m8n8.x4.shared.b16 {%0,%1,%2,%3}, [%4];" \
        : "=r"((r)[0]), "=r"((r)[1]), "=r"((r)[2]), "=r"((r)[3]) : "r"(addr))

__device__ __forceinline__ void mma_bf16(float* c, const uint32_t* a,
                                         uint32_t b0, uint32_t b1) {
    asm volatile("mma.sync.aligned.m16n8k16.row.col.f32.bf16.bf16.f32 "
        "{%0,%1,%2,%3}, {%4,%5,%6,%7}, {%8,%9}, {%0,%1,%2,%3};"
        : "+f"(c[0]), "+f"(c[1]), "+f"(c[2]), "+f"(c[3])
        : "r"(a[0]), "r"(a[1]), "r"(a[2]), "r"(a[3]), "r"(b0), "r"(b1));
}

__device__ __forceinline__ float sigmoidf_(float x) { return 1.0f / (1.0f + __expf(-x)); }
__device__ __forceinline__ unsigned short bf16_bits(__nv_bfloat16 h) {
    return *reinterpret_cast<unsigned short*>(&h);
}
__device__ __forceinline__ void split_bf16(float v, unsigned short& hi, unsigned short& lo) {
    __nv_bfloat16 h = __float2bfloat16(v);
    float r = v - __bfloat162float(h);
    __nv_bfloat16 l = __float2bfloat16(r);
    hi = bf16_bits(h); lo = bf16_bits(l);
}

// ---------------------------------------------------------------------------
// fp32 -> bf16 hi/lo split conversions
// ---------------------------------------------------------------------------
__global__ __launch_bounds__(256)
void convert_x_kernel(const float* __restrict__ x) {
    int i = blockIdx.x * blockDim.x + threadIdx.x;
    float4 v = ((const float4*)x)[i];
    ushort4 hi, lo;
    split_bf16(v.x, hi.x, lo.x); split_bf16(v.y, hi.y, lo.y);
    split_bf16(v.z, hi.z, lo.z); split_bf16(v.w, hi.w, lo.w);
    ((ushort4*)g_xhi)[i] = hi;
    ((ushort4*)g_xlo)[i] = lo;
}

__global__ __launch_bounds__(256)
void convert_w_kernel(const float* __restrict__ Wg, const float* __restrict__ Wv,
                      const float* __restrict__ Wd) {
    int i = blockIdx.x * blockDim.x + threadIdx.x;
    const int per = Dd * Dd / 4;
    int mat = i / per, rem = i - mat * per;
    const float* src = (mat == 0) ? Wg : (mat == 1) ? Wv : Wd;
    float4 v = ((const float4*)src)[rem];
    ushort4 hi, lo;
    split_bf16(v.x, hi.x, lo.x); split_bf16(v.y, hi.y, lo.y);
    split_bf16(v.z, hi.z, lo.z); split_bf16(v.w, hi.w, lo.w);
    ((ushort4*)g_whi)[i] = hi;
    ((ushort4*)g_wlo)[i] = lo;
}

// ---------------------------------------------------------------------------
// Stage loader (KC=32, 64B rows): 4 operand tiles, 128 rows x 64B each.
// Swizzle: seg' = seg ^ ((row>>1)&3)  (conflict-free for ldmatrix)
// ---------------------------------------------------------------------------
__device__ __forceinline__ void issue_stage(uint32_t sbase, int s,
    const __nv_bfloat16* a_hi, const __nv_bfloat16* a_lo,
    const __nv_bfloat16* b_hi, const __nv_bfloat16* b_lo,
    int kc, int tid)
{
    const __nv_bfloat16* srcs[4] = {a_hi, a_lo, b_hi, b_lo};
    uint32_t base = sbase + s * STAGE_BYTES;
    #pragma unroll
    for (int o = 0; o < 4; o++) {
        const __nv_bfloat16* src = srcs[o] + kc * KC;
        uint32_t dbase = base + o * TILE_BYTES;
        #pragma unroll
        for (int it = 0; it < 2; it++) {
            int u = tid + it * 256;          // 0..511
            int r = u >> 2, seg = u & 3;
            uint32_t dst = dbase + r * 64 + ((uint32_t)(seg ^ ((r >> 1) & 3)) << 4);
            cp_async16(dst, src + (size_t)r * Dd + seg * 8);
        }
    }
}

// ---------------------------------------------------------------------------
// bf16-split mma.sync GEMM: C[m,n] = sum_k A[m,k]*W[n,k]  (one of g/v/d per z)
// CTA 128x128, 8 warps (2x4), warp tile 64x32, 3-stage cp.async pipeline,
// 2 CTAs/SM (96KB smem, <=128 regs).
// ---------------------------------------------------------------------------
__global__ __launch_bounds__(256, 2)
void gemm_mma_kernel()
{
    extern __shared__ char smem[];
    const uint32_t sbase = smem_u32(smem);
    const int tid = threadIdx.x, lane = tid & 31, wid = tid >> 5;
    const int wm = wid >> 2, wn = wid & 3;
    const int m0 = blockIdx.y * TBM, n0 = blockIdx.x * TBN, mat = blockIdx.z;

    const __nv_bfloat16* a_hi = g_xhi + (size_t)m0 * Dd;
    const __nv_bfloat16* a_lo = g_xlo + (size_t)m0 * Dd;
    const __nv_bfloat16* b_hi = g_whi + ((size_t)mat * Dd + n0) * Dd;
    const __nv_bfloat16* b_lo = g_wlo + ((size_t)mat * Dd + n0) * Dd;

    issue_stage(sbase, 0, a_hi, a_lo, b_hi, b_lo, 0, tid); CP_COMMIT();
    issue_stage(sbase, 1, a_hi, a_lo, b_hi, b_lo, 1, tid); CP_COMMIT();

    float acc[4][4][4] = {};

    // per-lane ldmatrix addressing (row stride 64B)
    const int r8 = lane & 7, q = lane >> 3;
    const int a_row_loc = (q & 1) * 8 + r8;
    const int a_seg_add = q >> 1;            // k16 half
    const int b_row_loc = (q >> 1) * 8 + r8;
    const int b_seg_add = q & 1;
    const int swz = (r8 >> 1) & 3;           // per-lane swizzle term
    const uint32_t a_off0 = (uint32_t)(wm * 64 + a_row_loc) * 64;
    const uint32_t b_off0 = (uint32_t)(wn * 32 + b_row_loc) * 64;

    for (int kc = 0; kc < NKC; kc++) {
        if (kc + 2 < NKC) {
            issue_stage(sbase, (kc + 2) % STAGES, a_hi, a_lo, b_hi, b_lo, kc + 2, tid);
            CP_COMMIT();
            asm volatile("cp.async.wait_group 2;" ::: "memory");
        } else if (kc + 1 < NKC) {
            asm volatile("cp.async.wait_group 1;" ::: "memory");
        } else {
            asm volatile("cp.async.wait_group 0;" ::: "memory");
        }
        __syncthreads();

        const uint32_t st = sbase + (kc % STAGES) * STAGE_BYTES;
        #pragma unroll
        for (int ks = 0; ks < 2; ks++) {          // 2 x k16 steps within KC=32
            uint32_t ahi[4][4], alo[4][4];
            #pragma unroll
            for (int mi = 0; mi < 4; mi++) {
                uint32_t off = a_off0 + mi * (16 * 64)
                             + ((uint32_t)((ks * 2 + a_seg_add) ^ swz) << 4);
                LDSM4(ahi[mi], st + OFF_AHI + off);
                LDSM4(alo[mi], st + OFF_ALO + off);
            }
            uint32_t bhi[2][4], blo[2][4];
            #pragma unroll
            for (int j = 0; j < 2; j++) {
                uint32_t off = b_off0 + j * (16 * 64)
                             + ((uint32_t)((ks * 2 + b_seg_add) ^ swz) << 4);
                LDSM4(bhi[j], st + OFF_BHI + off);
                LDSM4(blo[j], st + OFF_BLO + off);
            }
            #pragma unroll
            for (int mi = 0; mi < 4; mi++) {
                #pragma unroll
                for (int ni = 0; ni < 4; ni++) {
                    const int j = ni >> 1, sub = ni & 1;
                    mma_bf16(acc[mi][ni], ahi[mi], bhi[j][sub*2], bhi[j][sub*2+1]);
                    mma_bf16(acc[mi][ni], ahi[mi], blo[j][sub*2], blo[j][sub*2+1]);
                    mma_bf16(acc[mi][ni], alo[mi], bhi[j][sub*2], bhi[j][sub*2+1]);
                }
            }
        }
        __syncthreads();
    }

    // epilogue: write raw fp32 GEMM result
    float* C = g_lin + (size_t)mat * MD;
    const int row_base = m0 + wm * 64 + (lane >> 2);
    const int col_base = n0 + wn * 32 + (lane & 3) * 2;
    #pragma unroll
    for (int mi = 0; mi < 4; mi++) {
        const int row = row_base + mi * 16;
        #pragma unroll
        for (int ni = 0; ni < 4; ni++) {
            const int col = col_base + ni * 8;
            *(float2*)&C[(size_t)row * Dd + col] =
                make_float2(acc[mi][ni][0], acc[mi][ni][1]);
            *(float2*)&C[(size_t)(row + 8) * Dd + col] =
                make_float2(acc[mi][ni][2], acc[mi][ni][3]);
        }
    }
}

// ---------------------------------------------------------------------------
// Fused gate + scan pass 1: per (channel, chunk) — read raw g/v/d, compute
// xs/a inline, local scan. Writes L into out and cumprod P into g_a.
// ---------------------------------------------------------------------------
__global__ __launch_bounds__(256)
void scan_gate_kernel(float* __restrict__ out,
                      const float* __restrict__ bg, const float* __restrict__ bv,
                      const float* __restrict__ bd)
{
    int gid = blockIdx.x * blockDim.x + threadIdx.x;
    int d    = gid & (Dd - 1);
    int rest = gid >> 10;
    int b    = rest & (Bb - 1);
    int c    = rest >> 2;

    const float bgd = bg[d], bvd = bv[d], bdd = bd[d];
    size_t base = ((size_t)b * Ss + c * TT) * Dd + d;
    float h = 0.0f, p = 1.0f;
    #pragma unroll 4
    for (int t = 0; t < TT; t++) {
        size_t idx = base + (size_t)t * Dd;
        float gg = g_lin[idx]          + bgd;
        float vv = g_lin[idx + MD]     + bvd;
        float dd = g_lin[idx + 2 * MD] + bdd;
        float xs = sigmoidf_(gg) * tanhf(vv);
        float a  = 0.001f + 0.998f * sigmoidf_(dd);
        h = fmaf(a, h, xs);
        p = p * a;
        out[idx] = h;
        g_a[idx] = p;
    }
}

// ---------------------------------------------------------------------------
// Scan pass 2: per-channel scan over chunk summaries -> carries.
// ---------------------------------------------------------------------------
__global__ __launch_bounds__(256)
void scan_carry_kernel(const float* __restrict__ out)
{
    int ch = blockIdx.x * blockDim.x + threadIdx.x;
    int d = ch & (Dd - 1);
    int b = ch >> 10;

    float cur = 0.0f;
    g_carry[ch] = 0.0f;
    #pragma unroll 8
    for (int c = 0; c < CHUNKS; c++) {
        size_t idx = ((size_t)b * Ss + c * TT + TT - 1) * Dd + d;
        float P = g_a[idx];
        float L = out[idx];
        cur = fmaf(P, cur, L);
        if (c + 1 < CHUNKS) g_carry[(c + 1) * NCH + ch] = cur;
    }
}

// ---------------------------------------------------------------------------
// Scan pass 3: fixup  out_t += carry[chunk] * P_t  (chunks >= 1)
// ---------------------------------------------------------------------------
__global__ __launch_bounds__(256)
void scan_fix_kernel(float* __restrict__ out)
{
    int e4  = blockIdx.x * blockDim.x + threadIdx.x;
    size_t idx = (size_t)e4 * 4;
    int m = (int)(idx >> 10);
    int s = m & (Ss - 1);
    int c = s >> 6;
    if (c == 0) return;
    int b = m >> 12;
    int d = (int)(idx & (Dd - 1));

    float4 P  = *(const float4*)&g_a[idx];
    float4 L  = *(float4*)&out[idx];
    float4 cr = *(const float4*)&g_carry[c * NCH + b * Dd + d];
    L.x = fmaf(cr.x, P.x, L.x);
    L.y = fmaf(cr.y, P.y, L.y);
    L.z = fmaf(cr.z, P.z, L.z);
    L.w = fmaf(cr.w, P.w, L.w);
    *(float4*)&out[idx] = L;
}

// ---------------------------------------------------------------------------
extern "C" void kernel_launch(void* const* d_in, const int* in_sizes, int n_in,
                              void* d_out, int out_size)
{
    const float* x  = (const float*)d_in[0];
    const float* Wg = (const float*)d_in[1];
    const float* bg = (const float*)d_in[2];
    const float* Wv = (const float*)d_in[3];
    const float* bv = (const float*)d_in[4];
    const float* Wd = (const float*)d_in[5];
    const float* bd = (const float*)d_in[6];
    float* out = (float*)d_out;

    cudaFuncSetAttribute(gemm_mma_kernel,
                         cudaFuncAttributeMaxDynamicSharedMemorySize, SMEM_TOTAL);

    convert_x_kernel<<<Mtot * Dd / 4 / 256, 256>>>(x);
    convert_w_kernel<<<3 * Dd * Dd / 4 / 256, 256>>>(Wg, Wv, Wd);

    dim3 grid(Dd / TBN, Mtot / TBM, 3);   // (8, 128, 3)
    gemm_mma_kernel<<<grid, 256, SMEM_TOTAL>>>();

    scan_gate_kernel<<<(NCH * CHUNKS) / 256, 256>>>(out, bg, bv, bd);
    scan_carry_kernel<<<NCH / 256, 256>>>(out);
    scan_fix_kernel  <<<(Mtot * Dd / 4) / 256, 256>>>(out);
}

// round 7
// speedup vs baseline: 7.6063x; 2.1038x over previous
#include <cuda_runtime.h>
#include <cuda_fp16.h>
#include <math.h>
#include <cstdint>

// Problem shape (fixed)
#define Bb    4
#define Ss    4096
#define Dd    1024
#define Mtot  (Bb * Ss)        // 16384 rows
#define MD    ((size_t)Mtot * Dd)
#define CHUNKS 64
#define TT     64
#define NCH   (Bb * Dd)

// GEMM tiling
#define TBM 128
#define TBN 128
#define KC  64                 // K chunk: 64 fp16 = 128B rows (SW128 swizzle)
#define NKC (Dd / KC)          // 16
#define STAGES 3
#define TILE_BYTES 16384       // 128 rows x 128B
#define STAGE_BYTES (2 * TILE_BYTES)        // A + B = 32KB
#define OFF_A 0
#define OFF_B 16384
#define SMEM_TOTAL (STAGES * STAGE_BYTES)   // 98304 -> 2 CTAs/SM

// Scratch (__device__ globals; no allocation allowed)
__device__ float g_a [Mtot * Dd];            // decay a -> in-chunk cumprod P
__device__ float g_carry[CHUNKS * NCH];
__device__ float g_lin[3ll * Mtot * Dd];     // raw GEMM outputs g,v,d
__device__ __half g_xh[Mtot * Dd];
__device__ __half g_wh[3 * Dd * Dd];

// ---------------- helpers ----------------
__device__ __forceinline__ uint32_t smem_u32(const void* p) {
    uint32_t a;
    asm("{ .reg .u64 t; cvta.to.shared.u64 t, %1; cvt.u32.u64 %0, t; }" : "=r"(a) : "l"(p));
    return a;
}
__device__ __forceinline__ void cp_async16(uint32_t s, const void* g) {
    asm volatile("{ .reg .u64 ga; cvta.to.global.u64 ga, %1; "
                 "cp.async.cg.shared.global [%0], [ga], 16; }"
                 :: "r"(s), "l"(g) : "memory");
}
#define CP_COMMIT() asm volatile("cp.async.commit_group;" ::: "memory")

#define LDSM4(r, addr) \
    asm volatile("ldmatrix.sync.aligned.m8n8.x4.shared.b16 {%0,%1,%2,%3}, [%4];" \
        : "=r"((r)[0]), "=r"((r)[1]), "=r"((r)[2]), "=r"((r)[3]) : "r"(addr))

__device__ __forceinline__ void mma_f16(float* c, const uint32_t* a,
                                        uint32_t b0, uint32_t b1) {
    asm volatile("mma.sync.aligned.m16n8k16.row.col.f32.f16.f16.f32 "
        "{%0,%1,%2,%3}, {%4,%5,%6,%7}, {%8,%9}, {%0,%1,%2,%3};"
        : "+f"(c[0]), "+f"(c[1]), "+f"(c[2]), "+f"(c[3])
        : "r"(a[0]), "r"(a[1]), "r"(a[2]), "r"(a[3]), "r"(b0), "r"(b1));
}

__device__ __forceinline__ float sigmoidf_(float x) { return 1.0f / (1.0f + __expf(-x)); }
// accurate fast tanh: 1 - 2/(exp(2v)+1); exact saturation at +/-inf
__device__ __forceinline__ float tanhf_(float v) {
    return 1.0f - 2.0f / (__expf(2.0f * v) + 1.0f);
}

// ---------------------------------------------------------------------------
// fp32 -> fp16 conversions
// ---------------------------------------------------------------------------
__global__ __launch_bounds__(256)
void convert_x_kernel(const float* __restrict__ x) {
    int i = blockIdx.x * blockDim.x + threadIdx.x;   // float4 index
    float4 v = ((const float4*)x)[i];
    __half2 h0 = __floats2half2_rn(v.x, v.y);
    __half2 h1 = __floats2half2_rn(v.z, v.w);
    ((__half2*)g_xh)[2 * i]     = h0;
    ((__half2*)g_xh)[2 * i + 1] = h1;
}

__global__ __launch_bounds__(256)
void convert_w_kernel(const float* __restrict__ Wg, const float* __restrict__ Wv,
                      const float* __restrict__ Wd) {
    int i = blockIdx.x * blockDim.x + threadIdx.x;   // float4 index over 3M elems
    const int per = Dd * Dd / 4;
    int mat = i / per, rem = i - mat * per;
    const float* src = (mat == 0) ? Wg : (mat == 1) ? Wv : Wd;
    float4 v = ((const float4*)src)[rem];
    __half2 h0 = __floats2half2_rn(v.x, v.y);
    __half2 h1 = __floats2half2_rn(v.z, v.w);
    ((__half2*)g_wh)[2 * i]     = h0;
    ((__half2*)g_wh)[2 * i + 1] = h1;
}

// ---------------------------------------------------------------------------
// Stage loader: A and B tiles, 128 rows x 128B, SW128-swizzled via cp.async.
// ---------------------------------------------------------------------------
__device__ __forceinline__ void issue_stage(uint32_t sbase, int s,
    const __half* a, const __half* b, int kc, int tid)
{
    const __half* srcs[2] = {a, b};
    uint32_t base = sbase + s * STAGE_BYTES;
    #pragma unroll
    for (int o = 0; o < 2; o++) {
        const __half* src = srcs[o] + kc * KC;
        uint32_t dbase = base + o * TILE_BYTES;
        #pragma unroll
        for (int it = 0; it < 4; it++) {
            int u = tid + it * 256;          // 0..1023
            int r = u >> 3, seg = u & 7;
            uint32_t dst = dbase + r * 128 + ((uint32_t)(seg ^ (r & 7)) << 4);
            cp_async16(dst, src + (size_t)r * Dd + seg * 8);
        }
    }
}

// ---------------------------------------------------------------------------
// fp16 mma.sync GEMM: C[m,n] = sum_k A[m,k]*W[n,k]  (one of g/v/d per z)
// CTA 128x128, 8 warps (2x4), warp tile 64x32, 3-stage cp.async pipeline.
// ---------------------------------------------------------------------------
__global__ __launch_bounds__(256, 2)
void gemm_mma_kernel()
{
    extern __shared__ char smem[];
    const uint32_t sbase = smem_u32(smem);
    const int tid = threadIdx.x, lane = tid & 31, wid = tid >> 5;
    const int wm = wid >> 2, wn = wid & 3;
    const int m0 = blockIdx.y * TBM, n0 = blockIdx.x * TBN, mat = blockIdx.z;

    const __half* a_src = g_xh + (size_t)m0 * Dd;
    const __half* b_src = g_wh + ((size_t)mat * Dd + n0) * Dd;

    issue_stage(sbase, 0, a_src, b_src, 0, tid); CP_COMMIT();
    issue_stage(sbase, 1, a_src, b_src, 1, tid); CP_COMMIT();

    float acc[4][4][4] = {};

    // per-lane ldmatrix addressing (row stride 128B, SW128)
    const int r8 = lane & 7, q = lane >> 3;
    const int a_row_loc = (q & 1) * 8 + r8;
    const int a_seg_add = q >> 1;            // k16 half
    const int b_row_loc = (q >> 1) * 8 + r8;
    const int b_seg_add = q & 1;
    const uint32_t a_off0 = (uint32_t)(wm * 64 + a_row_loc) * 128;
    const uint32_t b_off0 = (uint32_t)(wn * 32 + b_row_loc) * 128;

    for (int kc = 0; kc < NKC; kc++) {
        if (kc + 2 < NKC) {
            issue_stage(sbase, (kc + 2) % STAGES, a_src, b_src, kc + 2, tid);
            CP_COMMIT();
            asm volatile("cp.async.wait_group 2;" ::: "memory");
        } else if (kc + 1 < NKC) {
            asm volatile("cp.async.wait_group 1;" ::: "memory");
        } else {
            asm volatile("cp.async.wait_group 0;" ::: "memory");
        }
        __syncthreads();

        const uint32_t st = sbase + (kc % STAGES) * STAGE_BYTES;
        #pragma unroll
        for (int ks = 0; ks < 4; ks++) {          // 4 x k16 steps within KC=64
            uint32_t af[4][4];
            #pragma unroll
            for (int mi = 0; mi < 4; mi++) {
                uint32_t off = a_off0 + mi * (16 * 128)
                             + ((uint32_t)((ks * 2 + a_seg_add) ^ r8) << 4);
                LDSM4(af[mi], st + OFF_A + off);
            }
            uint32_t bf[2][4];
            #pragma unroll
            for (int j = 0; j < 2; j++) {
                uint32_t off = b_off0 + j * (16 * 128)
                             + ((uint32_t)((ks * 2 + b_seg_add) ^ r8) << 4);
                LDSM4(bf[j], st + OFF_B + off);
            }
            #pragma unroll
            for (int mi = 0; mi < 4; mi++) {
                #pragma unroll
                for (int ni = 0; ni < 4; ni++) {
                    const int j = ni >> 1, sub = ni & 1;
                    mma_f16(acc[mi][ni], af[mi], bf[j][sub*2], bf[j][sub*2+1]);
                }
            }
        }
        __syncthreads();
    }

    // epilogue: write raw fp32 GEMM result
    float* C = g_lin + (size_t)mat * MD;
    const int row_base = m0 + wm * 64 + (lane >> 2);
    const int col_base = n0 + wn * 32 + (lane & 3) * 2;
    #pragma unroll
    for (int mi = 0; mi < 4; mi++) {
        const int row = row_base + mi * 16;
        #pragma unroll
        for (int ni = 0; ni < 4; ni++) {
            const int col = col_base + ni * 8;
            *(float2*)&C[(size_t)row * Dd + col] =
                make_float2(acc[mi][ni][0], acc[mi][ni][1]);
            *(float2*)&C[(size_t)(row + 8) * Dd + col] =
                make_float2(acc[mi][ni][2], acc[mi][ni][3]);
        }
    }
}

// ---------------------------------------------------------------------------
// Fused gate + scan pass 1: read raw g/v/d, compute xs/a inline, local scan.
// Writes L into out and cumprod P into g_a.
// ---------------------------------------------------------------------------
__global__ __launch_bounds__(256)
void scan_gate_kernel(float* __restrict__ out,
                      const float* __restrict__ bg, const float* __restrict__ bv,
                      const float* __restrict__ bd)
{
    int gid = blockIdx.x * blockDim.x + threadIdx.x;
    int d    = gid & (Dd - 1);
    int rest = gid >> 10;
    int b    = rest & (Bb - 1);
    int c    = rest >> 2;

    const float bgd = bg[d], bvd = bv[d], bdd = bd[d];
    size_t base = ((size_t)b * Ss + c * TT) * Dd + d;
    float h = 0.0f, p = 1.0f;
    #pragma unroll 4
    for (int t = 0; t < TT; t++) {
        size_t idx = base + (size_t)t * Dd;
        float gg = g_lin[idx]          + bgd;
        float vv = g_lin[idx + MD]     + bvd;
        float dd = g_lin[idx + 2 * MD] + bdd;
        float xs = sigmoidf_(gg) * tanhf_(vv);
        float a  = 0.001f + 0.998f * sigmoidf_(dd);
        h = fmaf(a, h, xs);
        p = p * a;
        out[idx] = h;
        g_a[idx] = p;
    }
}

// ---------------------------------------------------------------------------
// Scan pass 2: per-channel scan over chunk summaries -> carries.
// ---------------------------------------------------------------------------
__global__ __launch_bounds__(256)
void scan_carry_kernel(const float* __restrict__ out)
{
    int ch = blockIdx.x * blockDim.x + threadIdx.x;
    int d = ch & (Dd - 1);
    int b = ch >> 10;

    float cur = 0.0f;
    g_carry[ch] = 0.0f;
    #pragma unroll 8
    for (int c = 0; c < CHUNKS; c++) {
        size_t idx = ((size_t)b * Ss + c * TT + TT - 1) * Dd + d;
        float P = g_a[idx];
        float L = out[idx];
        cur = fmaf(P, cur, L);
        if (c + 1 < CHUNKS) g_carry[(c + 1) * NCH + ch] = cur;
    }
}

// ---------------------------------------------------------------------------
// Scan pass 3: fixup  out_t += carry[chunk] * P_t  (chunks >= 1)
// ---------------------------------------------------------------------------
__global__ __launch_bounds__(256)
void scan_fix_kernel(float* __restrict__ out)
{
    int e4  = blockIdx.x * blockDim.x + threadIdx.x;
    size_t idx = (size_t)e4 * 4;
    int m = (int)(idx >> 10);
    int s = m & (Ss - 1);
    int c = s >> 6;
    if (c == 0) return;
    int b = m >> 12;
    int d = (int)(idx & (Dd - 1));

    float4 P  = *(const float4*)&g_a[idx];
    float4 L  = *(float4*)&out[idx];
    float4 cr = *(const float4*)&g_carry[c * NCH + b * Dd + d];
    L.x = fmaf(cr.x, P.x, L.x);
    L.y = fmaf(cr.y, P.y, L.y);
    L.z = fmaf(cr.z, P.z, L.z);
    L.w = fmaf(cr.w, P.w, L.w);
    *(float4*)&out[idx] = L;
}

// ---------------------------------------------------------------------------
extern "C" void kernel_launch(void* const* d_in, const int* in_sizes, int n_in,
                              void* d_out, int out_size)
{
    const float* x  = (const float*)d_in[0];
    const float* Wg = (const float*)d_in[1];
    const float* bg = (const float*)d_in[2];
    const float* Wv = (const float*)d_in[3];
    const float* bv = (const float*)d_in[4];
    const float* Wd = (const float*)d_in[5];
    const float* bd = (const float*)d_in[6];
    float* out = (float*)d_out;

    cudaFuncSetAttribute(gemm_mma_kernel,
                         cudaFuncAttributeMaxDynamicSharedMemorySize, SMEM_TOTAL);

    convert_x_kernel<<<Mtot * Dd / 4 / 256, 256>>>(x);
    convert_w_kernel<<<3 * Dd * Dd / 4 / 256, 256>>>(Wg, Wv, Wd);

    dim3 grid(Dd / TBN, Mtot / TBM, 3);   // (8, 128, 3)
    gemm_mma_kernel<<<grid, 256, SMEM_TOTAL>>>();

    scan_gate_kernel<<<(NCH * CHUNKS) / 256, 256>>>(out, bg, bv, bd);
    scan_carry_kernel<<<NCH / 256, 256>>>(out);
    scan_fix_kernel  <<<(Mtot * Dd / 4) / 256, 256>>>(out);
}